// round 1
// baseline (speedup 1.0000x reference)
#include <cuda_runtime.h>
#include <math.h>

// ---------------- problem constants ----------------
#define NB     4
#define LSEQ   8192
#define DMODEL 256
#define NHEAD  8
#define HDIM   32
#define WNW    9
#define PAD    4
#define PLEN   8200          // L + 2*PAD
#define NROW   32800         // NB * PLEN
#define MROW   32768         // NB * LSEQ
#define ATT_SCALE 0.17677669529663687f  // 1/sqrt(32)

// ---------------- scratch (device globals; no runtime alloc) ----------------
__device__ float g_qkv[(size_t)NROW * 768];       // per padded row: [q(256)|k(256)|v(256)]
__device__ float g_posqkv[WNW * 768];             // pos @ [Wq|Wk|Wv]
__device__ float g_pp[NHEAD * 81];                // posq.posk per (h,qi,ki), pre-scaled
__device__ float g_R1[(size_t)NROW * NHEAD * 9];  // xq[r,h].posk[w,h], pre-scaled
__device__ float g_R2[(size_t)NROW * NHEAD * 9];  // posq[w,h].xk[r,h], pre-scaled
__device__ float g_XX[(size_t)NROW * NHEAD * 17]; // xq[r,h].xk[r+d-8,h], pre-scaled
__device__ float g_ctx[(size_t)MROW * DMODEL];
__device__ float g_tmp[(size_t)MROW * DMODEL];
__device__ float g_res[(size_t)MROW * DMODEL];

// ---------------- K1: pos @ [Wq|Wk|Wv] ----------------
__global__ void k_posproj(const float* __restrict__ pos,
                          const float* __restrict__ Wq,
                          const float* __restrict__ Wk,
                          const float* __restrict__ Wv) {
    int t = blockIdx.x * blockDim.x + threadIdx.x;
    if (t >= WNW * 768) return;
    int w = t / 768, j = t % 768;
    const float* W = (j < 256) ? Wq : ((j < 512) ? Wk : Wv);
    int jj = j & 255;
    const float* p = pos + w * DMODEL;
    float acc = 0.f;
    for (int d = 0; d < DMODEL; d++) acc = fmaf(p[d], W[d * DMODEL + jj], acc);
    g_posqkv[t] = acc;
}

// ---------------- K1b: PP table ----------------
__global__ void k_pp(void) {
    int t = blockIdx.x * blockDim.x + threadIdx.x;
    if (t >= NHEAD * 81) return;
    int h = t / 81, qi = (t / 9) % 9, ki = t % 9;
    float acc = 0.f;
    const float* pq = g_posqkv + qi * 768 + h * HDIM;
    const float* pk = g_posqkv + ki * 768 + 256 + h * HDIM;
    for (int d = 0; d < HDIM; d++) acc = fmaf(pq[d], pk[d], acc);
    g_pp[t] = acc * ATT_SCALE;
}

// ---------------- generic 128x128x16 fp32 GEMM, K=256 ----------------
// MODE 0: g_qkv[32800x768] = Xpad @ [Wq|Wk|Wv]      (A gathered from x with zero pad)
// MODE 1: g_tmp = g_ctx @ Wo + addv(x)              (M=32768, N=256)
// MODE 2: g_tmp = g_res @ Wout^T + addv(b_out) + g_res
template <int MODE>
__global__ void __launch_bounds__(256) k_gemm(const float* __restrict__ xin,
                                              const float* __restrict__ Wq,
                                              const float* __restrict__ Wk,
                                              const float* __restrict__ Wv,
                                              const float* __restrict__ addv) {
    __shared__ float As[16][128];
    __shared__ float Bs[16][128];
    int tid = threadIdx.x;
    int ttx = tid & 15, tty = tid >> 4;
    int rb = blockIdx.x * 128;
    int jb = blockIdx.y * 128;

    const float* Bmat;
    int j0;
    if (MODE == 0) { Bmat = (jb < 256) ? Wq : (jb < 512 ? Wk : Wv); j0 = jb & 255; }
    else           { Bmat = Wq; j0 = jb; }

    float acc[8][8];
#pragma unroll
    for (int i = 0; i < 8; i++)
#pragma unroll
        for (int j = 0; j < 8; j++) acc[i][j] = 0.f;

    for (int kb = 0; kb < 256; kb += 16) {
        // A tile 128x16
#pragma unroll
        for (int i = 0; i < 2; i++) {
            int id = tid + i * 256;
            int row = id >> 2;
            int c4 = (id & 3) * 4;
            float4 v = make_float4(0.f, 0.f, 0.f, 0.f);
            int gr = rb + row;
            if (MODE == 0) {
                if (gr < NROW) {
                    int b = gr / PLEN;
                    int r = gr - b * PLEN;
                    int xr = r - PAD;
                    if ((unsigned)xr < (unsigned)LSEQ)
                        v = *(const float4*)(xin + ((size_t)(b * LSEQ + xr)) * 256 + kb + c4);
                }
            } else if (MODE == 1) {
                v = *(const float4*)(g_ctx + (size_t)gr * 256 + kb + c4);
            } else {
                v = *(const float4*)(g_res + (size_t)gr * 256 + kb + c4);
            }
            As[c4 + 0][row] = v.x; As[c4 + 1][row] = v.y;
            As[c4 + 2][row] = v.z; As[c4 + 3][row] = v.w;
        }
        // B tile 16x128
#pragma unroll
        for (int i = 0; i < 2; i++) {
            int id = tid + i * 256;
            if (MODE == 2) {
                // B[k][n] = Wout[(jb+n)*256 + k]  (transpose load)
                int nn = id >> 2;
                int c4 = (id & 3) * 4;
                float4 v = *(const float4*)(Bmat + ((size_t)(j0 + nn)) * 256 + kb + c4);
                Bs[c4 + 0][nn] = v.x; Bs[c4 + 1][nn] = v.y;
                Bs[c4 + 2][nn] = v.z; Bs[c4 + 3][nn] = v.w;
            } else {
                int kr = id >> 5;
                int c4 = (id & 31) * 4;
                float4 v = *(const float4*)(Bmat + ((size_t)(kb + kr)) * 256 + j0 + c4);
                *(float4*)&Bs[kr][c4] = v;
            }
        }
        __syncthreads();
#pragma unroll
        for (int k = 0; k < 16; k++) {
            float a[8], bv[8];
#pragma unroll
            for (int i = 0; i < 8; i++) a[i] = As[k][tty * 8 + i];
#pragma unroll
            for (int j = 0; j < 8; j++) bv[j] = Bs[k][ttx * 8 + j];
#pragma unroll
            for (int i = 0; i < 8; i++)
#pragma unroll
                for (int j = 0; j < 8; j++) acc[i][j] = fmaf(a[i], bv[j], acc[i][j]);
        }
        __syncthreads();
    }
    // epilogue
#pragma unroll
    for (int i = 0; i < 8; i++) {
        int gr = rb + tty * 8 + i;
        if (MODE == 0 && gr >= NROW) continue;
#pragma unroll
        for (int j = 0; j < 8; j += 4) {
            int col = ttx * 8 + j;
            float4 v = make_float4(acc[i][j], acc[i][j + 1], acc[i][j + 2], acc[i][j + 3]);
            if (MODE == 0) {
                *(float4*)(g_qkv + (size_t)gr * 768 + jb + col) = v;
            } else if (MODE == 1) {
                float4 ax = *(const float4*)(addv + (size_t)gr * 256 + jb + col);
                v.x += ax.x; v.y += ax.y; v.z += ax.z; v.w += ax.w;
                *(float4*)(g_tmp + (size_t)gr * 256 + jb + col) = v;
            } else {
                float4 bb = *(const float4*)(addv + jb + col);
                float4 ar = *(const float4*)(g_res + (size_t)gr * 256 + jb + col);
                v.x += bb.x + ar.x; v.y += bb.y + ar.y;
                v.z += bb.z + ar.z; v.w += bb.w + ar.w;
                *(float4*)(g_tmp + (size_t)gr * 256 + jb + col) = v;
            }
        }
    }
}

// ---------------- K3: score tables XX / R1 / R2 ----------------
// smem layout [row][h][33] so (lr,h) lanes hit 32 distinct banks.
#define TROWS 32
#define HALO  48
#define HSTR  33
#define RSTR  264  // 8*33
#define TAB_SMEM ((HALO + 18) * RSTR * 4)

__global__ void __launch_bounds__(256) k_tables(void) {
    extern __shared__ float sm[];
    float* s_xk = sm;                   // [48][8][33]
    float* s_pq = sm + HALO * RSTR;     // [9][8][33]
    float* s_pk = s_pq + 9 * RSTR;      // [9][8][33]
    int b = blockIdx.y;
    int r0 = blockIdx.x * TROWS;
    int tid = threadIdx.x;

    for (int idx = tid; idx < HALO * 256; idx += 256) {
        int lr = idx >> 8, d = idx & 255;
        int gr = r0 - 8 + lr;
        float v = 0.f;
        if (gr >= 0 && gr < PLEN)
            v = g_qkv[((size_t)(b * PLEN + gr)) * 768 + 256 + d];
        s_xk[lr * RSTR + (d >> 5) * HSTR + (d & 31)] = v;
    }
    for (int idx = tid; idx < 9 * 256; idx += 256) {
        int w = idx >> 8, d = idx & 255;
        int so = (d >> 5) * HSTR + (d & 31);
        s_pq[w * RSTR + so] = g_posqkv[w * 768 + d];
        s_pk[w * RSTR + so] = g_posqkv[w * 768 + 256 + d];
    }
    __syncthreads();

    int h = tid & 7, lr = tid >> 3;   // lr in 0..31
    int r = r0 + lr;
    if (r >= PLEN) return;
    size_t grow = (size_t)(b * PLEN + r);

    float xq[32], xk[32];
    const float* qrow = g_qkv + grow * 768 + h * HDIM;
#pragma unroll
    for (int i = 0; i < 32; i += 4) {
        float4 v = *(const float4*)(qrow + i);
        xq[i] = v.x; xq[i + 1] = v.y; xq[i + 2] = v.z; xq[i + 3] = v.w;
    }
    const float* myk = s_xk + (lr + 8) * RSTR + h * HSTR;
#pragma unroll
    for (int i = 0; i < 32; i++) xk[i] = myk[i];

#pragma unroll
    for (int w = 0; w < 9; w++) {
        const float* pk = s_pk + w * RSTR + h * HSTR;
        float acc = 0.f;
#pragma unroll
        for (int i = 0; i < 32; i++) acc = fmaf(xq[i], pk[i], acc);
        g_R1[(grow * 8 + h) * 9 + w] = acc * ATT_SCALE;
    }
#pragma unroll
    for (int w = 0; w < 9; w++) {
        const float* pq = s_pq + w * RSTR + h * HSTR;
        float acc = 0.f;
#pragma unroll
        for (int i = 0; i < 32; i++) acc = fmaf(pq[i], xk[i], acc);
        g_R2[(grow * 8 + h) * 9 + w] = acc * ATT_SCALE;
    }
#pragma unroll
    for (int dd = 0; dd < 17; dd++) {
        int rr = r + dd - 8;
        float acc = 0.f;
        if (rr >= 0 && rr < PLEN) {
            const float* kk = s_xk + (lr + dd) * RSTR + h * HSTR;
#pragma unroll
            for (int i = 0; i < 32; i++) acc = fmaf(xq[i], kk[i], acc);
        }
        g_XX[(grow * 8 + h) * 17 + dd] = acc * ATT_SCALE;
    }
}

// ---------------- K5: softmax weights + ctx ----------------
#define WPB 16
#define ATT_SMEM ((WPB * 648 + WPB * 72 + 9 * 256 + 648) * 4)

__global__ void __launch_bounds__(256) k_attn(void) {
    extern __shared__ float sm[];
    float* s_p  = sm;                       // [WPB][8][9][9]
    float* s_w  = sm + WPB * 648;           // [WPB][8][9]
    float* s_pv = s_w + WPB * 72;           // [9][256]
    float* s_pp = s_pv + 9 * 256;           // [648]
    int tid = threadIdx.x;
    int wbase = blockIdx.x * WPB;
    int b = wbase / LSEQ;
    int n0 = wbase - b * LSEQ;

    for (int i = tid; i < 9 * 256; i += 256)
        s_pv[i] = g_posqkv[(i >> 8) * 768 + 512 + (i & 255)];
    for (int i = tid; i < 648; i += 256) s_pp[i] = g_pp[i];
    __syncthreads();

    // phase 1: softmax per (window, head, q-row)
    for (int t = tid; t < WPB * 72; t += 256) {
        int wi = t / 72;
        int rem = t - wi * 72;
        int h = rem / 9, qi = rem - h * 9;
        int n = n0 + wi;
        size_t rq = (size_t)(b * PLEN + n + qi);
        const float* xx = g_XX + (rq * 8 + h) * 17 + (8 - qi);
        const float* r1 = g_R1 + (rq * 8 + h) * 9;
        float s[9], m = -1e30f;
#pragma unroll
        for (int ki = 0; ki < 9; ki++) {
            size_t rk = (size_t)(b * PLEN + n + ki);
            float v = xx[ki] + r1[ki] + g_R2[(rk * 8 + h) * 9 + qi]
                    + s_pp[h * 81 + qi * 9 + ki];
            s[ki] = v; m = fmaxf(m, v);
        }
        float sum = 0.f;
#pragma unroll
        for (int ki = 0; ki < 9; ki++) { s[ki] = __expf(s[ki] - m); sum += s[ki]; }
        float inv = 1.f / sum;
#pragma unroll
        for (int ki = 0; ki < 9; ki++)
            s_p[wi * 648 + h * 81 + qi * 9 + ki] = s[ki] * inv;
    }
    __syncthreads();

    // phase 2: w[k] = sum_q attn[q,k]
    for (int t = tid; t < WPB * 72; t += 256) {
        int wi = t / 72;
        int rem = t - wi * 72;
        int h = rem / 9, ki = rem - h * 9;
        float acc = 0.f;
#pragma unroll
        for (int qi = 0; qi < 9; qi++) acc += s_p[wi * 648 + h * 81 + qi * 9 + ki];
        s_w[wi * 72 + h * 9 + ki] = acc;
    }
    __syncthreads();

    // phase 3: ctx[n][j] = sum_k w[h(j),k] * (xv[n+k][j] + posv[k][j])
    int j = tid;
    int h = j >> 5;
    for (int wi = 0; wi < WPB; wi++) {
        int n = n0 + wi;
        float acc = 0.f;
#pragma unroll
        for (int k = 0; k < 9; k++) {
            float v = g_qkv[((size_t)(b * PLEN + n + k)) * 768 + 512 + j]
                    + s_pv[k * 256 + j];
            acc = fmaf(s_w[wi * 72 + h * 9 + k], v, acc);
        }
        g_ctx[((size_t)(b * LSEQ) + n) * 256 + j] = acc;
    }
}

// ---------------- LayerNorm (warp per row), optional relu ----------------
__global__ void __launch_bounds__(256) k_ln(const float* __restrict__ gamma,
                                            const float* __restrict__ beta,
                                            float* __restrict__ outPtr,
                                            int mode /*0: ->g_res, 1: ->outPtr + relu*/) {
    int row = blockIdx.x * 8 + (threadIdx.x >> 5);
    int lane = threadIdx.x & 31;
    const float* p = g_tmp + (size_t)row * 256;
    float v[8], s = 0.f, s2 = 0.f;
#pragma unroll
    for (int i = 0; i < 8; i++) {
        v[i] = p[lane + i * 32];
        s += v[i]; s2 = fmaf(v[i], v[i], s2);
    }
#pragma unroll
    for (int o = 16; o; o >>= 1) {
        s  += __shfl_xor_sync(0xffffffffu, s, o);
        s2 += __shfl_xor_sync(0xffffffffu, s2, o);
    }
    float m = s * (1.f / 256.f);
    float var = s2 * (1.f / 256.f) - m * m;
    float inv = rsqrtf(var + 1e-5f);
    float* dst = mode ? outPtr : g_res;
#pragma unroll
    for (int i = 0; i < 8; i++) {
        int j = lane + i * 32;
        float o = (v[i] - m) * inv * gamma[j] + beta[j];
        if (mode) o = fmaxf(o, 0.f);
        dst[(size_t)row * 256 + j] = o;
    }
}

// ---------------- launch ----------------
extern "C" void kernel_launch(void* const* d_in, const int* in_sizes, int n_in,
                              void* d_out, int out_size) {
    const float* x    = (const float*)d_in[0];
    const float* Wq   = (const float*)d_in[1];
    const float* Wk   = (const float*)d_in[2];
    const float* Wv   = (const float*)d_in[3];
    const float* Wo   = (const float*)d_in[4];
    const float* pos  = (const float*)d_in[5];
    const float* Wout = (const float*)d_in[6];
    const float* bout = (const float*)d_in[7];
    const float* g1   = (const float*)d_in[8];
    const float* b1   = (const float*)d_in[9];
    const float* g2   = (const float*)d_in[10];
    const float* b2   = (const float*)d_in[11];
    float* out = (float*)d_out;

    cudaFuncSetAttribute(k_tables, cudaFuncAttributeMaxDynamicSharedMemorySize, TAB_SMEM);
    cudaFuncSetAttribute(k_attn,   cudaFuncAttributeMaxDynamicSharedMemorySize, ATT_SMEM);

    k_posproj<<<27, 256>>>(pos, Wq, Wk, Wv);
    k_pp<<<3, 256>>>();

    // qkv projection: 32800 x 768
    k_gemm<0><<<dim3(257, 6), 256>>>(x, Wq, Wk, Wv, nullptr);

    // score tables
    k_tables<<<dim3(257, NB), 256, TAB_SMEM>>>();

    // attention -> ctx
    k_attn<<<(NB * LSEQ) / WPB, 256, ATT_SMEM>>>();

    // y = x + ctx @ Wo -> g_tmp ; LN1 -> g_res
    k_gemm<1><<<dim3(256, 2), 256>>>(nullptr, Wo, nullptr, nullptr, x);
    k_ln<<<4096, 256>>>(g1, b1, nullptr, 0);

    // z = g_res @ Wout^T + bout + g_res -> g_tmp ; LN2 + relu -> out
    k_gemm<2><<<dim3(256, 2), 256>>>(nullptr, Wout, nullptr, nullptr, bout);
    k_ln<<<4096, 256>>>(g2, b2, out, 1);
}

// round 3
// speedup vs baseline: 1.5443x; 1.5443x over previous
#include <cuda_runtime.h>
#include <cstdint>
#include <math.h>

// ---------------- problem constants ----------------
#define NB     4
#define LSEQ   8192
#define DMODEL 256
#define NHEAD  8
#define HDIM   32
#define WNW    9
#define PAD    4
#define PLEN   8200          // L + 2*PAD
#define NROW   32800         // NB * PLEN
#define MROW   32768         // NB * LSEQ
#define ATT_SCALE 0.17677669529663687f  // 1/sqrt(32)

// ---------------- scratch (device globals; no runtime alloc) ----------------
__device__ float g_qkv[(size_t)NROW * 768];       // per padded row: [q(256)|k(256)|v(256)]
__device__ float g_posqkv[WNW * 768];             // pos @ [Wq|Wk|Wv]
__device__ float g_pp[NHEAD * 81];                // posq.posk per (h,qi,ki), pre-scaled
__device__ float g_R1[(size_t)NROW * NHEAD * 9];
__device__ float g_R2[(size_t)NROW * NHEAD * 9];
__device__ float g_XX[(size_t)NROW * NHEAD * 17];
__device__ float g_ctx[(size_t)MROW * DMODEL];
__device__ float g_tmp[(size_t)MROW * DMODEL];
__device__ float g_res[(size_t)MROW * DMODEL];
__device__ float g_wT[4 * 256 * 256];             // W^T for Wq,Wk,Wv,Wo in [n][k]

__device__ __forceinline__ float tf32r(float x) {
    uint32_t u;
    asm("cvt.rna.tf32.f32 %0, %1;" : "=r"(u) : "f"(x));
    return __uint_as_float(u);
}

// ---------------- K0: transpose weights into g_wT [mat][n][k] ----------------
__global__ void k_wt(const float* __restrict__ Wq, const float* __restrict__ Wk,
                     const float* __restrict__ Wv, const float* __restrict__ Wo) {
    __shared__ float t[32][33];
    const float* W = (blockIdx.z == 0) ? Wq : (blockIdx.z == 1) ? Wk
                   : (blockIdx.z == 2) ? Wv : Wo;
    int bx = blockIdx.x * 32, by = blockIdx.y * 32;
    int tid = threadIdx.x;
    int c = tid & 31, r0 = tid >> 5;
#pragma unroll
    for (int i = 0; i < 4; i++) {
        int r = r0 + i * 8;
        t[r][c] = W[(size_t)(by + r) * 256 + bx + c];
    }
    __syncthreads();
#pragma unroll
    for (int i = 0; i < 4; i++) {
        int r = r0 + i * 8;
        g_wT[(size_t)blockIdx.z * 65536 + (size_t)(bx + r) * 256 + by + c] = t[c][r];
    }
}

// ---------------- K1: pos @ [Wq|Wk|Wv] ----------------
__global__ void k_posproj(const float* __restrict__ pos,
                          const float* __restrict__ Wq,
                          const float* __restrict__ Wk,
                          const float* __restrict__ Wv) {
    int t = blockIdx.x * blockDim.x + threadIdx.x;
    if (t >= WNW * 768) return;
    int w = t / 768, j = t % 768;
    const float* W = (j < 256) ? Wq : ((j < 512) ? Wk : Wv);
    int jj = j & 255;
    const float* p = pos + w * DMODEL;
    float acc = 0.f;
    for (int d = 0; d < DMODEL; d++) acc = fmaf(p[d], W[d * DMODEL + jj], acc);
    g_posqkv[t] = acc;
}

// ---------------- K1b: PP table ----------------
__global__ void k_pp(void) {
    int t = blockIdx.x * blockDim.x + threadIdx.x;
    if (t >= NHEAD * 81) return;
    int h = t / 81, qi = (t / 9) % 9, ki = t % 9;
    float acc = 0.f;
    const float* pq = g_posqkv + qi * 768 + h * HDIM;
    const float* pk = g_posqkv + ki * 768 + 256 + h * HDIM;
    for (int d = 0; d < HDIM; d++) acc = fmaf(pq[d], pk[d], acc);
    g_pp[t] = acc * ATT_SCALE;
}

// ---------------- tf32 mma.sync GEMM: 128x128 tile, K=256 ----------------
// 8 warps in 2(M)x4(N); each warp 64x32 via 4x4 m16n8k8 fragments.
// MODE 0: g_qkv = Xpad @ [Wq|Wk|Wv]                grid (257, 6)
// MODE 1: g_tmp = g_ctx @ Wo + x                   grid (256, 2)
// MODE 2: g_tmp = g_res @ Wout^T + bout + g_res    grid (256, 2)
template <int MODE>
__global__ void __launch_bounds__(256) k_tgemm(const float* __restrict__ xin,
                                               const float* __restrict__ Bparam,
                                               const float* __restrict__ addv) {
    __shared__ float As[2][16][132];   // [buf][k][m]
    __shared__ float Bs[2][16][132];   // [buf][k][n]
    int tid = threadIdx.x;
    int rb = blockIdx.x * 128;
    int jb = blockIdx.y * 128;

    const float* Bmat;
    int j0;
    if (MODE == 0) { Bmat = g_wT + (size_t)(blockIdx.y >> 1) * 65536; j0 = (blockIdx.y & 1) * 128; }
    else if (MODE == 1) { Bmat = g_wT + (size_t)3 * 65536; j0 = jb; }
    else { Bmat = Bparam; j0 = jb; }

    // per-thread load slots: 2 float4 for A, 2 for B per chunk
    const float* ap[2]; bool av[2];
    const float* bp[2];
    int arow[2], ac4[2];
#pragma unroll
    for (int i = 0; i < 2; i++) {
        int id = tid + i * 256;
        int row = id >> 2, c4 = (id & 3) * 4;
        arow[i] = row; ac4[i] = c4;
        int gr = rb + row;
        if (MODE == 0) {
            int b = gr / PLEN;
            int r = gr - b * PLEN;
            int xr = r - PAD;
            av[i] = (gr < NROW) && ((unsigned)xr < (unsigned)LSEQ);
            ap[i] = xin + ((size_t)b * LSEQ + (size_t)((unsigned)xr < (unsigned)LSEQ ? xr : 0)) * 256 + c4;
        } else {
            av[i] = true;
            ap[i] = (MODE == 1 ? g_ctx : g_res) + (size_t)gr * 256 + c4;
        }
        bp[i] = Bmat + (size_t)(j0 + row) * 256 + c4;
    }

    int lane = tid & 31;
    int w = tid >> 5;
    int wm = (w & 1) * 64;        // warp M offset
    int wn = (w >> 1) * 32;       // warp N offset
    int gid = lane >> 2;          // groupID
    int tig = lane & 3;           // thread-in-group

    float c[4][4][4];             // [mt][nt][c0..c3]
#pragma unroll
    for (int mt = 0; mt < 4; mt++)
#pragma unroll
        for (int nt = 0; nt < 4; nt++)
#pragma unroll
            for (int q = 0; q < 4; q++) c[mt][nt][q] = 0.f;

    float4 pa[2], pb[2];
    // prologue: load + store chunk 0
#pragma unroll
    for (int i = 0; i < 2; i++) {
        pa[i] = av[i] ? *(const float4*)(ap[i]) : make_float4(0.f, 0.f, 0.f, 0.f);
        pb[i] = *(const float4*)(bp[i]);
    }
#pragma unroll
    for (int i = 0; i < 2; i++) {
        int row = arow[i], c4 = ac4[i];
        As[0][c4 + 0][row] = tf32r(pa[i].x); As[0][c4 + 1][row] = tf32r(pa[i].y);
        As[0][c4 + 2][row] = tf32r(pa[i].z); As[0][c4 + 3][row] = tf32r(pa[i].w);
        Bs[0][c4 + 0][row] = tf32r(pb[i].x); Bs[0][c4 + 1][row] = tf32r(pb[i].y);
        Bs[0][c4 + 2][row] = tf32r(pb[i].z); Bs[0][c4 + 3][row] = tf32r(pb[i].w);
    }
    __syncthreads();

#pragma unroll 1
    for (int kc = 0; kc < 16; kc++) {
        int buf = kc & 1;
        if (kc < 15) {
            int kb = (kc + 1) * 16;
#pragma unroll
            for (int i = 0; i < 2; i++) {
                pa[i] = av[i] ? *(const float4*)(ap[i] + kb) : make_float4(0.f, 0.f, 0.f, 0.f);
                pb[i] = *(const float4*)(bp[i] + kb);
            }
        }
#pragma unroll
        for (int kh = 0; kh < 2; kh++) {
            int k0 = kh * 8;
            uint32_t af[4][4], bf[4][2];
#pragma unroll
            for (int mt = 0; mt < 4; mt++) {
                int m = wm + mt * 16;
                af[mt][0] = __float_as_uint(As[buf][k0 + tig][m + gid]);
                af[mt][1] = __float_as_uint(As[buf][k0 + tig][m + gid + 8]);
                af[mt][2] = __float_as_uint(As[buf][k0 + tig + 4][m + gid]);
                af[mt][3] = __float_as_uint(As[buf][k0 + tig + 4][m + gid + 8]);
            }
#pragma unroll
            for (int nt = 0; nt < 4; nt++) {
                int n = wn + nt * 8;
                bf[nt][0] = __float_as_uint(Bs[buf][k0 + tig][n + gid]);
                bf[nt][1] = __float_as_uint(Bs[buf][k0 + tig + 4][n + gid]);
            }
#pragma unroll
            for (int mt = 0; mt < 4; mt++)
#pragma unroll
                for (int nt = 0; nt < 4; nt++) {
                    asm volatile(
                        "mma.sync.aligned.m16n8k8.row.col.f32.tf32.tf32.f32 "
                        "{%0,%1,%2,%3}, {%4,%5,%6,%7}, {%8,%9}, {%0,%1,%2,%3};"
                        : "+f"(c[mt][nt][0]), "+f"(c[mt][nt][1]),
                          "+f"(c[mt][nt][2]), "+f"(c[mt][nt][3])
                        : "r"(af[mt][0]), "r"(af[mt][1]), "r"(af[mt][2]), "r"(af[mt][3]),
                          "r"(bf[nt][0]), "r"(bf[nt][1]));
                }
        }
        if (kc < 15) {
            int nb = buf ^ 1;
#pragma unroll
            for (int i = 0; i < 2; i++) {
                int row = arow[i], c4 = ac4[i];
                As[nb][c4 + 0][row] = tf32r(pa[i].x); As[nb][c4 + 1][row] = tf32r(pa[i].y);
                As[nb][c4 + 2][row] = tf32r(pa[i].z); As[nb][c4 + 3][row] = tf32r(pa[i].w);
                Bs[nb][c4 + 0][row] = tf32r(pb[i].x); Bs[nb][c4 + 1][row] = tf32r(pb[i].y);
                Bs[nb][c4 + 2][row] = tf32r(pb[i].z); Bs[nb][c4 + 3][row] = tf32r(pb[i].w);
            }
        }
        __syncthreads();
    }

    // epilogue
#pragma unroll
    for (int mt = 0; mt < 4; mt++) {
#pragma unroll
        for (int rr = 0; rr < 2; rr++) {
            int gr = rb + wm + mt * 16 + gid + rr * 8;
            if (MODE == 0 && gr >= NROW) continue;
#pragma unroll
            for (int nt = 0; nt < 4; nt++) {
                int col = wn + nt * 8 + 2 * tig;
                float v0 = c[mt][nt][rr * 2 + 0];
                float v1 = c[mt][nt][rr * 2 + 1];
                if (MODE == 0) {
                    float2* dst = (float2*)(g_qkv + (size_t)gr * 768 + jb + col);
                    *dst = make_float2(v0, v1);
                } else if (MODE == 1) {
                    const float2 a2 = *(const float2*)(addv + (size_t)gr * 256 + jb + col);
                    float2* dst = (float2*)(g_tmp + (size_t)gr * 256 + jb + col);
                    *dst = make_float2(v0 + a2.x, v1 + a2.y);
                } else {
                    const float2 r2 = *(const float2*)(g_res + (size_t)gr * 256 + jb + col);
                    const float2 b2 = *(const float2*)(addv + jb + col);
                    float2* dst = (float2*)(g_tmp + (size_t)gr * 256 + jb + col);
                    *dst = make_float2(v0 + r2.x + b2.x, v1 + r2.y + b2.y);
                }
            }
        }
    }
}

// ---------------- K3: score tables XX / R1 / R2 ----------------
#define TROWS 32
#define HALO  48
#define HSTR  33
#define RSTR  264  // 8*33
#define TAB_SMEM ((HALO + 18) * RSTR * 4)

__global__ void __launch_bounds__(256) k_tables(void) {
    extern __shared__ float sm[];
    float* s_xk = sm;                   // [48][8][33]
    float* s_pq = sm + HALO * RSTR;     // [9][8][33]
    float* s_pk = s_pq + 9 * RSTR;      // [9][8][33]
    int b = blockIdx.y;
    int r0 = blockIdx.x * TROWS;
    int tid = threadIdx.x;

    for (int idx = tid; idx < HALO * 256; idx += 256) {
        int lr = idx >> 8, d = idx & 255;
        int gr = r0 - 8 + lr;
        float v = 0.f;
        if (gr >= 0 && gr < PLEN)
            v = g_qkv[((size_t)(b * PLEN + gr)) * 768 + 256 + d];
        s_xk[lr * RSTR + (d >> 5) * HSTR + (d & 31)] = v;
    }
    for (int idx = tid; idx < 9 * 256; idx += 256) {
        int w = idx >> 8, d = idx & 255;
        int so = (d >> 5) * HSTR + (d & 31);
        s_pq[w * RSTR + so] = g_posqkv[w * 768 + d];
        s_pk[w * RSTR + so] = g_posqkv[w * 768 + 256 + d];
    }
    __syncthreads();

    int h = tid & 7, lr = tid >> 3;
    int r = r0 + lr;
    if (r >= PLEN) return;
    size_t grow = (size_t)(b * PLEN + r);

    float xq[32], xk[32];
    const float* qrow = g_qkv + grow * 768 + h * HDIM;
#pragma unroll
    for (int i = 0; i < 32; i += 4) {
        float4 v = *(const float4*)(qrow + i);
        xq[i] = v.x; xq[i + 1] = v.y; xq[i + 2] = v.z; xq[i + 3] = v.w;
    }
    const float* myk = s_xk + (lr + 8) * RSTR + h * HSTR;
#pragma unroll
    for (int i = 0; i < 32; i++) xk[i] = myk[i];

#pragma unroll
    for (int w = 0; w < 9; w++) {
        const float* pk = s_pk + w * RSTR + h * HSTR;
        float acc = 0.f;
#pragma unroll
        for (int i = 0; i < 32; i++) acc = fmaf(xq[i], pk[i], acc);
        g_R1[(grow * 8 + h) * 9 + w] = acc * ATT_SCALE;
    }
#pragma unroll
    for (int w = 0; w < 9; w++) {
        const float* pq = s_pq + w * RSTR + h * HSTR;
        float acc = 0.f;
#pragma unroll
        for (int i = 0; i < 32; i++) acc = fmaf(pq[i], xk[i], acc);
        g_R2[(grow * 8 + h) * 9 + w] = acc * ATT_SCALE;
    }
#pragma unroll
    for (int dd = 0; dd < 17; dd++) {
        int rr = r + dd - 8;
        float acc = 0.f;
        if (rr >= 0 && rr < PLEN) {
            const float* kk = s_xk + (lr + dd) * RSTR + h * HSTR;
#pragma unroll
            for (int i = 0; i < 32; i++) acc = fmaf(xq[i], kk[i], acc);
        }
        g_XX[(grow * 8 + h) * 17 + dd] = acc * ATT_SCALE;
    }
}

// ---------------- K5: softmax weights + ctx ----------------
#define WPB 16
#define ATT_SMEM ((WPB * 648 + WPB * 72 + 9 * 256 + 648) * 4)

__global__ void __launch_bounds__(256) k_attn(void) {
    extern __shared__ float sm[];
    float* s_p  = sm;                       // [WPB][8][9][9]
    float* s_w  = sm + WPB * 648;           // [WPB][8][9]
    float* s_pv = s_w + WPB * 72;           // [9][256]
    float* s_pp = s_pv + 9 * 256;           // [648]
    int tid = threadIdx.x;
    int wbase = blockIdx.x * WPB;
    int b = wbase / LSEQ;
    int n0 = wbase - b * LSEQ;

    for (int i = tid; i < 9 * 256; i += 256)
        s_pv[i] = g_posqkv[(i >> 8) * 768 + 512 + (i & 255)];
    for (int i = tid; i < 648; i += 256) s_pp[i] = g_pp[i];
    __syncthreads();

    for (int t = tid; t < WPB * 72; t += 256) {
        int wi = t / 72;
        int rem = t - wi * 72;
        int h = rem / 9, qi = rem - h * 9;
        int n = n0 + wi;
        size_t rq = (size_t)(b * PLEN + n + qi);
        const float* xx = g_XX + (rq * 8 + h) * 17 + (8 - qi);
        const float* r1 = g_R1 + (rq * 8 + h) * 9;
        float s[9], m = -1e30f;
#pragma unroll
        for (int ki = 0; ki < 9; ki++) {
            size_t rk = (size_t)(b * PLEN + n + ki);
            float v = xx[ki] + r1[ki] + g_R2[(rk * 8 + h) * 9 + qi]
                    + s_pp[h * 81 + qi * 9 + ki];
            s[ki] = v; m = fmaxf(m, v);
        }
        float sum = 0.f;
#pragma unroll
        for (int ki = 0; ki < 9; ki++) { s[ki] = __expf(s[ki] - m); sum += s[ki]; }
        float inv = 1.f / sum;
#pragma unroll
        for (int ki = 0; ki < 9; ki++)
            s_p[wi * 648 + h * 81 + qi * 9 + ki] = s[ki] * inv;
    }
    __syncthreads();

    for (int t = tid; t < WPB * 72; t += 256) {
        int wi = t / 72;
        int rem = t - wi * 72;
        int h = rem / 9, ki = rem - h * 9;
        float acc = 0.f;
#pragma unroll
        for (int qi = 0; qi < 9; qi++) acc += s_p[wi * 648 + h * 81 + qi * 9 + ki];
        s_w[wi * 72 + h * 9 + ki] = acc;
    }
    __syncthreads();

    int j = tid;
    int h = j >> 5;
    for (int wi = 0; wi < WPB; wi++) {
        int n = n0 + wi;
        float acc = 0.f;
#pragma unroll
        for (int k = 0; k < 9; k++) {
            float v = g_qkv[((size_t)(b * PLEN + n + k)) * 768 + 512 + j]
                    + s_pv[k * 256 + j];
            acc = fmaf(s_w[wi * 72 + h * 9 + k], v, acc);
        }
        g_ctx[((size_t)(b * LSEQ) + n) * 256 + j] = acc;
    }
}

// ---------------- LayerNorm (warp per row), optional relu ----------------
__global__ void __launch_bounds__(256) k_ln(const float* __restrict__ gamma,
                                            const float* __restrict__ beta,
                                            float* __restrict__ outPtr,
                                            int mode) {
    int row = blockIdx.x * 8 + (threadIdx.x >> 5);
    int lane = threadIdx.x & 31;
    const float* p = g_tmp + (size_t)row * 256;
    float v[8], s = 0.f, s2 = 0.f;
#pragma unroll
    for (int i = 0; i < 8; i++) {
        v[i] = p[lane + i * 32];
        s += v[i]; s2 = fmaf(v[i], v[i], s2);
    }
#pragma unroll
    for (int o = 16; o; o >>= 1) {
        s  += __shfl_xor_sync(0xffffffffu, s, o);
        s2 += __shfl_xor_sync(0xffffffffu, s2, o);
    }
    float m = s * (1.f / 256.f);
    float var = s2 * (1.f / 256.f) - m * m;
    float inv = rsqrtf(var + 1e-5f);
    float* dst = mode ? outPtr : g_res;
#pragma unroll
    for (int i = 0; i < 8; i++) {
        int j = lane + i * 32;
        float o = (v[i] - m) * inv * gamma[j] + beta[j];
        if (mode) o = fmaxf(o, 0.f);
        dst[(size_t)row * 256 + j] = o;
    }
}

// ---------------- launch ----------------
extern "C" void kernel_launch(void* const* d_in, const int* in_sizes, int n_in,
                              void* d_out, int out_size) {
    const float* x    = (const float*)d_in[0];
    const float* Wq   = (const float*)d_in[1];
    const float* Wk   = (const float*)d_in[2];
    const float* Wv   = (const float*)d_in[3];
    const float* Wo   = (const float*)d_in[4];
    const float* pos  = (const float*)d_in[5];
    const float* Wout = (const float*)d_in[6];
    const float* bout = (const float*)d_in[7];
    const float* g1   = (const float*)d_in[8];
    const float* b1   = (const float*)d_in[9];
    const float* g2   = (const float*)d_in[10];
    const float* b2   = (const float*)d_in[11];
    float* out = (float*)d_out;

    cudaFuncSetAttribute(k_tables, cudaFuncAttributeMaxDynamicSharedMemorySize, TAB_SMEM);
    cudaFuncSetAttribute(k_attn,   cudaFuncAttributeMaxDynamicSharedMemorySize, ATT_SMEM);

    k_wt<<<dim3(8, 8, 4), 256>>>(Wq, Wk, Wv, Wo);
    k_posproj<<<27, 256>>>(pos, Wq, Wk, Wv);
    k_pp<<<3, 256>>>();

    // qkv projection (tensor cores via mma.sync tf32)
    k_tgemm<0><<<dim3(257, 6), 256>>>(x, nullptr, nullptr);

    // score tables
    k_tables<<<dim3(257, NB), 256, TAB_SMEM>>>();

    // attention -> ctx
    k_attn<<<(NB * LSEQ) / WPB, 256, ATT_SMEM>>>();

    // y = x + ctx @ Wo -> g_tmp ; LN1 -> g_res
    k_tgemm<1><<<dim3(256, 2), 256>>>(nullptr, nullptr, x);
    k_ln<<<4096, 256>>>(g1, b1, nullptr, 0);

    // z = g_res @ Wout^T + bout + g_res -> g_tmp ; LN2 + relu -> out
    k_tgemm<2><<<dim3(256, 2), 256>>>(nullptr, Wout, bout);
    k_ln<<<4096, 256>>>(g2, b2, out, 1);
}

// round 4
// speedup vs baseline: 1.7394x; 1.1264x over previous
#include <cuda_runtime.h>
#include <cstdint>
#include <math.h>

// ---------------- problem constants ----------------
#define NB     4
#define LSEQ   8192
#define DMODEL 256
#define NHEAD  8
#define HDIM   32
#define WNW    9
#define PAD    4
#define PLEN   8200          // L + 2*PAD
#define NROW   32800         // NB * PLEN
#define MROW   32768         // NB * LSEQ
#define ATT_SCALE 0.17677669529663687f  // 1/sqrt(32)

// ---------------- scratch (device globals; no runtime alloc) ----------------
__device__ float g_qkv[(size_t)NROW * 768];       // per padded row: [q(256)|k(256)|v(256)]
__device__ float g_posqkv[WNW * 768];             // pos @ [Wq|Wk|Wv]
__device__ float g_pp[NHEAD * 81];                // posq.posk per (h,qi,ki), pre-scaled
__device__ float g_R1[(size_t)NROW * NHEAD * 9];
__device__ float g_R2[(size_t)NROW * NHEAD * 9];
__device__ float g_XX[(size_t)NROW * NHEAD * 17];
__device__ float g_ctx[(size_t)MROW * DMODEL];
__device__ float g_tmp[(size_t)MROW * DMODEL];
__device__ float g_res[(size_t)MROW * DMODEL];
__device__ float g_wT[4 * 256 * 256];             // W^T for Wq,Wk,Wv,Wo in [n][k]

__device__ __forceinline__ float tf32r(float x) {
    uint32_t u;
    asm("cvt.rna.tf32.f32 %0, %1;" : "=r"(u) : "f"(x));
    return __uint_as_float(u);
}

// ---------------- K0: transpose weights into g_wT [mat][n][k] ----------------
__global__ void k_wt(const float* __restrict__ Wq, const float* __restrict__ Wk,
                     const float* __restrict__ Wv, const float* __restrict__ Wo) {
    __shared__ float t[32][33];
    const float* W = (blockIdx.z == 0) ? Wq : (blockIdx.z == 1) ? Wk
                   : (blockIdx.z == 2) ? Wv : Wo;
    int bx = blockIdx.x * 32, by = blockIdx.y * 32;
    int tid = threadIdx.x;
    int c = tid & 31, r0 = tid >> 5;
#pragma unroll
    for (int i = 0; i < 4; i++) {
        int r = r0 + i * 8;
        t[r][c] = W[(size_t)(by + r) * 256 + bx + c];
    }
    __syncthreads();
#pragma unroll
    for (int i = 0; i < 4; i++) {
        int r = r0 + i * 8;
        g_wT[(size_t)blockIdx.z * 65536 + (size_t)(bx + r) * 256 + by + c] = t[c][r];
    }
}

// ---------------- K1: pos @ [Wq|Wk|Wv] ----------------
__global__ void k_posproj(const float* __restrict__ pos,
                          const float* __restrict__ Wq,
                          const float* __restrict__ Wk,
                          const float* __restrict__ Wv) {
    int t = blockIdx.x * blockDim.x + threadIdx.x;
    if (t >= WNW * 768) return;
    int w = t / 768, j = t % 768;
    const float* W = (j < 256) ? Wq : ((j < 512) ? Wk : Wv);
    int jj = j & 255;
    const float* p = pos + w * DMODEL;
    float acc = 0.f;
    for (int d = 0; d < DMODEL; d++) acc = fmaf(p[d], W[d * DMODEL + jj], acc);
    g_posqkv[t] = acc;
}

// ---------------- K1b: PP table ----------------
__global__ void k_pp(void) {
    int t = blockIdx.x * blockDim.x + threadIdx.x;
    if (t >= NHEAD * 81) return;
    int h = t / 81, qi = (t / 9) % 9, ki = t % 9;
    float acc = 0.f;
    const float* pq = g_posqkv + qi * 768 + h * HDIM;
    const float* pk = g_posqkv + ki * 768 + 256 + h * HDIM;
    for (int d = 0; d < HDIM; d++) acc = fmaf(pq[d], pk[d], acc);
    g_pp[t] = acc * ATT_SCALE;
}

// ---------------- tf32 mma.sync GEMM: 128x128 tile, K=256 ----------------
// SMEM tiles in [row][16] layout with 2-row XOR swizzle:
//   off(r, k) = r*16 + (k ^ (4*((r>>1)&3)))  -> conflict-free STS.128 and frag LDS.
// 8 warps in 2(M)x4(N); each warp 64x32 via 4x4 m16n8k8 fragments.
template <int MODE>
__global__ void __launch_bounds__(256) k_tgemm(const float* __restrict__ xin,
                                               const float* __restrict__ Bparam,
                                               const float* __restrict__ addv) {
    __shared__ float As[2][2048];   // [buf][row*16 + swz(k)]
    __shared__ float Bs[2][2048];
    int tid = threadIdx.x;
    int rb = blockIdx.x * 128;
    int jb = blockIdx.y * 128;

    const float* Bmat;
    int j0;
    if (MODE == 0) { Bmat = g_wT + (size_t)(blockIdx.y >> 1) * 65536; j0 = (blockIdx.y & 1) * 128; }
    else if (MODE == 1) { Bmat = g_wT + (size_t)3 * 65536; j0 = jb; }
    else { Bmat = Bparam; j0 = jb; }

    // per-thread load slots: 2 float4 for A, 2 for B per chunk
    const float* ap[2]; bool av[2];
    const float* bp[2];
    int soff[2];
#pragma unroll
    for (int i = 0; i < 2; i++) {
        int id = tid + i * 256;
        int row = id >> 2, c4 = (id & 3) * 4;
        soff[i] = row * 16 + (c4 ^ (4 * ((row >> 1) & 3)));
        int gr = rb + row;
        if (MODE == 0) {
            int b = gr / PLEN;
            int r = gr - b * PLEN;
            int xr = r - PAD;
            av[i] = (gr < NROW) && ((unsigned)xr < (unsigned)LSEQ);
            ap[i] = xin + ((size_t)b * LSEQ + (size_t)((unsigned)xr < (unsigned)LSEQ ? xr : 0)) * 256 + c4;
        } else {
            av[i] = true;
            ap[i] = (MODE == 1 ? g_ctx : g_res) + (size_t)gr * 256 + c4;
        }
        bp[i] = Bmat + (size_t)(j0 + row) * 256 + c4;
    }

    int lane = tid & 31;
    int w = tid >> 5;
    int wm = (w & 1) * 64;        // warp M offset
    int wn = (w >> 1) * 32;       // warp N offset
    int gid = lane >> 2;          // groupID
    int tig = lane & 3;           // thread-in-group
    int swz = 4 * ((gid >> 1) & 3);

    float c[4][4][4];             // [mt][nt][c0..c3]
#pragma unroll
    for (int mt = 0; mt < 4; mt++)
#pragma unroll
        for (int nt = 0; nt < 4; nt++)
#pragma unroll
            for (int q = 0; q < 4; q++) c[mt][nt][q] = 0.f;

    float4 pa[2], pb[2];
    // prologue: load + store chunk 0
#pragma unroll
    for (int i = 0; i < 2; i++) {
        pa[i] = av[i] ? *(const float4*)(ap[i]) : make_float4(0.f, 0.f, 0.f, 0.f);
        pb[i] = *(const float4*)(bp[i]);
    }
#pragma unroll
    for (int i = 0; i < 2; i++) {
        float4 va = make_float4(tf32r(pa[i].x), tf32r(pa[i].y), tf32r(pa[i].z), tf32r(pa[i].w));
        float4 vb = make_float4(tf32r(pb[i].x), tf32r(pb[i].y), tf32r(pb[i].z), tf32r(pb[i].w));
        *(float4*)&As[0][soff[i]] = va;
        *(float4*)&Bs[0][soff[i]] = vb;
    }
    __syncthreads();

#pragma unroll 1
    for (int kc = 0; kc < 16; kc++) {
        int buf = kc & 1;
        if (kc < 15) {
            int kb = (kc + 1) * 16;
#pragma unroll
            for (int i = 0; i < 2; i++) {
                pa[i] = av[i] ? *(const float4*)(ap[i] + kb) : make_float4(0.f, 0.f, 0.f, 0.f);
                pb[i] = *(const float4*)(bp[i] + kb);
            }
        }
#pragma unroll
        for (int kh = 0; kh < 2; kh++) {
            int k0 = kh * 8;
            int ka = (k0 + tig) ^ swz;
            int kb2 = (k0 + tig + 4) ^ swz;
            uint32_t af[4][4], bf[4][2];
#pragma unroll
            for (int mt = 0; mt < 4; mt++) {
                int mbase = (wm + mt * 16 + gid) * 16;
                af[mt][0] = __float_as_uint(As[buf][mbase + ka]);
                af[mt][1] = __float_as_uint(As[buf][mbase + 128 + ka]);
                af[mt][2] = __float_as_uint(As[buf][mbase + kb2]);
                af[mt][3] = __float_as_uint(As[buf][mbase + 128 + kb2]);
            }
#pragma unroll
            for (int nt = 0; nt < 4; nt++) {
                int nbase = (wn + nt * 8 + gid) * 16;
                bf[nt][0] = __float_as_uint(Bs[buf][nbase + ka]);
                bf[nt][1] = __float_as_uint(Bs[buf][nbase + kb2]);
            }
#pragma unroll
            for (int mt = 0; mt < 4; mt++)
#pragma unroll
                for (int nt = 0; nt < 4; nt++) {
                    asm volatile(
                        "mma.sync.aligned.m16n8k8.row.col.f32.tf32.tf32.f32 "
                        "{%0,%1,%2,%3}, {%4,%5,%6,%7}, {%8,%9}, {%0,%1,%2,%3};"
                        : "+f"(c[mt][nt][0]), "+f"(c[mt][nt][1]),
                          "+f"(c[mt][nt][2]), "+f"(c[mt][nt][3])
                        : "r"(af[mt][0]), "r"(af[mt][1]), "r"(af[mt][2]), "r"(af[mt][3]),
                          "r"(bf[nt][0]), "r"(bf[nt][1]));
                }
        }
        if (kc < 15) {
            int nb = buf ^ 1;
#pragma unroll
            for (int i = 0; i < 2; i++) {
                float4 va = make_float4(tf32r(pa[i].x), tf32r(pa[i].y), tf32r(pa[i].z), tf32r(pa[i].w));
                float4 vb = make_float4(tf32r(pb[i].x), tf32r(pb[i].y), tf32r(pb[i].z), tf32r(pb[i].w));
                *(float4*)&As[nb][soff[i]] = va;
                *(float4*)&Bs[nb][soff[i]] = vb;
            }
        }
        __syncthreads();
    }

    // epilogue
#pragma unroll
    for (int mt = 0; mt < 4; mt++) {
#pragma unroll
        for (int rr = 0; rr < 2; rr++) {
            int gr = rb + wm + mt * 16 + gid + rr * 8;
            if (MODE == 0 && gr >= NROW) continue;
#pragma unroll
            for (int nt = 0; nt < 4; nt++) {
                int col = wn + nt * 8 + 2 * tig;
                float v0 = c[mt][nt][rr * 2 + 0];
                float v1 = c[mt][nt][rr * 2 + 1];
                if (MODE == 0) {
                    float2* dst = (float2*)(g_qkv + (size_t)gr * 768 + jb + col);
                    *dst = make_float2(v0, v1);
                } else if (MODE == 1) {
                    const float2 a2 = *(const float2*)(addv + (size_t)gr * 256 + jb + col);
                    float2* dst = (float2*)(g_tmp + (size_t)gr * 256 + jb + col);
                    *dst = make_float2(v0 + a2.x, v1 + a2.y);
                } else {
                    const float2 r2 = *(const float2*)(g_res + (size_t)gr * 256 + jb + col);
                    const float2 b2 = *(const float2*)(addv + jb + col);
                    float2* dst = (float2*)(g_tmp + (size_t)gr * 256 + jb + col);
                    *dst = make_float2(v0 + r2.x + b2.x, v1 + r2.y + b2.y);
                }
            }
        }
    }
}

// ---------------- K3: score tables XX / R1 / R2 ----------------
#define TROWS 32
#define HALO  48
#define HSTR  33
#define RSTR  264  // 8*33
#define TAB_SMEM ((HALO + 18) * RSTR * 4)

__global__ void __launch_bounds__(256) k_tables(void) {
    extern __shared__ float sm[];
    float* s_xk = sm;                   // [48][8][33]
    float* s_pq = sm + HALO * RSTR;     // [9][8][33]
    float* s_pk = s_pq + 9 * RSTR;      // [9][8][33]
    int b = blockIdx.y;
    int r0 = blockIdx.x * TROWS;
    int tid = threadIdx.x;

    for (int idx = tid; idx < HALO * 256; idx += 256) {
        int lr = idx >> 8, d = idx & 255;
        int gr = r0 - 8 + lr;
        float v = 0.f;
        if (gr >= 0 && gr < PLEN)
            v = g_qkv[((size_t)(b * PLEN + gr)) * 768 + 256 + d];
        s_xk[lr * RSTR + (d >> 5) * HSTR + (d & 31)] = v;
    }
    for (int idx = tid; idx < 9 * 256; idx += 256) {
        int w = idx >> 8, d = idx & 255;
        int so = (d >> 5) * HSTR + (d & 31);
        s_pq[w * RSTR + so] = g_posqkv[w * 768 + d];
        s_pk[w * RSTR + so] = g_posqkv[w * 768 + 256 + d];
    }
    __syncthreads();

    int h = tid & 7, lr = tid >> 3;
    int r = r0 + lr;
    if (r >= PLEN) return;
    size_t grow = (size_t)(b * PLEN + r);

    float xq[32], xk[32];
    const float* qrow = g_qkv + grow * 768 + h * HDIM;
#pragma unroll
    for (int i = 0; i < 32; i += 4) {
        float4 v = *(const float4*)(qrow + i);
        xq[i] = v.x; xq[i + 1] = v.y; xq[i + 2] = v.z; xq[i + 3] = v.w;
    }
    const float* myk = s_xk + (lr + 8) * RSTR + h * HSTR;
#pragma unroll
    for (int i = 0; i < 32; i++) xk[i] = myk[i];

#pragma unroll
    for (int w = 0; w < 9; w++) {
        const float* pk = s_pk + w * RSTR + h * HSTR;
        float acc = 0.f;
#pragma unroll
        for (int i = 0; i < 32; i++) acc = fmaf(xq[i], pk[i], acc);
        g_R1[(grow * 8 + h) * 9 + w] = acc * ATT_SCALE;
    }
#pragma unroll
    for (int w = 0; w < 9; w++) {
        const float* pq = s_pq + w * RSTR + h * HSTR;
        float acc = 0.f;
#pragma unroll
        for (int i = 0; i < 32; i++) acc = fmaf(pq[i], xk[i], acc);
        g_R2[(grow * 8 + h) * 9 + w] = acc * ATT_SCALE;
    }
#pragma unroll
    for (int dd = 0; dd < 17; dd++) {
        int rr = r + dd - 8;
        float acc = 0.f;
        if (rr >= 0 && rr < PLEN) {
            const float* kk = s_xk + (lr + dd) * RSTR + h * HSTR;
#pragma unroll
            for (int i = 0; i < 32; i++) acc = fmaf(xq[i], kk[i], acc);
        }
        g_XX[(grow * 8 + h) * 17 + dd] = acc * ATT_SCALE;
    }
}

// ---------------- K5: softmax weights + ctx ----------------
#define WPB 16
#define ATT_SMEM ((WPB * 648 + WPB * 72 + 9 * 256 + 648) * 4)

__global__ void __launch_bounds__(256) k_attn(void) {
    extern __shared__ float sm[];
    float* s_p  = sm;                       // [WPB][8][9][9]
    float* s_w  = sm + WPB * 648;           // [WPB][8][9]
    float* s_pv = s_w + WPB * 72;           // [9][256]
    float* s_pp = s_pv + 9 * 256;           // [648]
    int tid = threadIdx.x;
    int wbase = blockIdx.x * WPB;
    int b = wbase / LSEQ;
    int n0 = wbase - b * LSEQ;

    for (int i = tid; i < 9 * 256; i += 256)
        s_pv[i] = g_posqkv[(i >> 8) * 768 + 512 + (i & 255)];
    for (int i = tid; i < 648; i += 256) s_pp[i] = g_pp[i];
    __syncthreads();

    for (int t = tid; t < WPB * 72; t += 256) {
        int wi = t / 72;
        int rem = t - wi * 72;
        int h = rem / 9, qi = rem - h * 9;
        int n = n0 + wi;
        size_t rq = (size_t)(b * PLEN + n + qi);
        const float* xx = g_XX + (rq * 8 + h) * 17 + (8 - qi);
        const float* r1 = g_R1 + (rq * 8 + h) * 9;
        float s[9], m = -1e30f;
#pragma unroll
        for (int ki = 0; ki < 9; ki++) {
            size_t rk = (size_t)(b * PLEN + n + ki);
            float v = xx[ki] + r1[ki] + g_R2[(rk * 8 + h) * 9 + qi]
                    + s_pp[h * 81 + qi * 9 + ki];
            s[ki] = v; m = fmaxf(m, v);
        }
        float sum = 0.f;
#pragma unroll
        for (int ki = 0; ki < 9; ki++) { s[ki] = __expf(s[ki] - m); sum += s[ki]; }
        float inv = 1.f / sum;
#pragma unroll
        for (int ki = 0; ki < 9; ki++)
            s_p[wi * 648 + h * 81 + qi * 9 + ki] = s[ki] * inv;
    }
    __syncthreads();

    for (int t = tid; t < WPB * 72; t += 256) {
        int wi = t / 72;
        int rem = t - wi * 72;
        int h = rem / 9, ki = rem - h * 9;
        float acc = 0.f;
#pragma unroll
        for (int qi = 0; qi < 9; qi++) acc += s_p[wi * 648 + h * 81 + qi * 9 + ki];
        s_w[wi * 72 + h * 9 + ki] = acc;
    }
    __syncthreads();

    int j = tid;
    int h = j >> 5;
    for (int wi = 0; wi < WPB; wi++) {
        int n = n0 + wi;
        float acc = 0.f;
#pragma unroll
        for (int k = 0; k < 9; k++) {
            float v = g_qkv[((size_t)(b * PLEN + n + k)) * 768 + 512 + j]
                    + s_pv[k * 256 + j];
            acc = fmaf(s_w[wi * 72 + h * 9 + k], v, acc);
        }
        g_ctx[((size_t)(b * LSEQ) + n) * 256 + j] = acc;
    }
}

// ---------------- LayerNorm (warp per row), optional relu ----------------
__global__ void __launch_bounds__(256) k_ln(const float* __restrict__ gamma,
                                            const float* __restrict__ beta,
                                            float* __restrict__ outPtr,
                                            int mode) {
    int row = blockIdx.x * 8 + (threadIdx.x >> 5);
    int lane = threadIdx.x & 31;
    const float* p = g_tmp + (size_t)row * 256;
    float v[8], s = 0.f, s2 = 0.f;
#pragma unroll
    for (int i = 0; i < 8; i++) {
        v[i] = p[lane + i * 32];
        s += v[i]; s2 = fmaf(v[i], v[i], s2);
    }
#pragma unroll
    for (int o = 16; o; o >>= 1) {
        s  += __shfl_xor_sync(0xffffffffu, s, o);
        s2 += __shfl_xor_sync(0xffffffffu, s2, o);
    }
    float m = s * (1.f / 256.f);
    float var = s2 * (1.f / 256.f) - m * m;
    float inv = rsqrtf(var + 1e-5f);
    float* dst = mode ? outPtr : g_res;
#pragma unroll
    for (int i = 0; i < 8; i++) {
        int j = lane + i * 32;
        float o = (v[i] - m) * inv * gamma[j] + beta[j];
        if (mode) o = fmaxf(o, 0.f);
        dst[(size_t)row * 256 + j] = o;
    }
}

// ---------------- launch ----------------
extern "C" void kernel_launch(void* const* d_in, const int* in_sizes, int n_in,
                              void* d_out, int out_size) {
    const float* x    = (const float*)d_in[0];
    const float* Wq   = (const float*)d_in[1];
    const float* Wk   = (const float*)d_in[2];
    const float* Wv   = (const float*)d_in[3];
    const float* Wo   = (const float*)d_in[4];
    const float* pos  = (const float*)d_in[5];
    const float* Wout = (const float*)d_in[6];
    const float* bout = (const float*)d_in[7];
    const float* g1   = (const float*)d_in[8];
    const float* b1   = (const float*)d_in[9];
    const float* g2   = (const float*)d_in[10];
    const float* b2   = (const float*)d_in[11];
    float* out = (float*)d_out;

    cudaFuncSetAttribute(k_tables, cudaFuncAttributeMaxDynamicSharedMemorySize, TAB_SMEM);
    cudaFuncSetAttribute(k_attn,   cudaFuncAttributeMaxDynamicSharedMemorySize, ATT_SMEM);

    k_wt<<<dim3(8, 8, 4), 256>>>(Wq, Wk, Wv, Wo);
    k_posproj<<<27, 256>>>(pos, Wq, Wk, Wv);
    k_pp<<<3, 256>>>();

    // qkv projection (tensor cores via mma.sync tf32)
    k_tgemm<0><<<dim3(257, 6), 256>>>(x, nullptr, nullptr);

    // score tables
    k_tables<<<dim3(257, NB), 256, TAB_SMEM>>>();

    // attention -> ctx
    k_attn<<<(NB * LSEQ) / WPB, 256, ATT_SMEM>>>();

    // y = x + ctx @ Wo -> g_tmp ; LN1 -> g_res
    k_tgemm<1><<<dim3(256, 2), 256>>>(nullptr, nullptr, x);
    k_ln<<<4096, 256>>>(g1, b1, nullptr, 0);

    // z = g_res @ Wout^T + bout + g_res -> g_tmp ; LN2 + relu -> out
    k_tgemm<2><<<dim3(256, 2), 256>>>(nullptr, Wout, bout);
    k_ln<<<4096, 256>>>(g2, b2, out, 1);
}

// round 5
// speedup vs baseline: 1.7934x; 1.0311x over previous
#include <cuda_runtime.h>
#include <cstdint>
#include <math.h>

// ---------------- problem constants ----------------
#define NB     4
#define LSEQ   8192
#define DMODEL 256
#define NHEAD  8
#define HDIM   32
#define WNW    9
#define PAD    4
#define PLEN   8200          // L + 2*PAD
#define NROW   32800         // NB * PLEN
#define MROW   32768         // NB * LSEQ
#define ATT_SCALE 0.17677669529663687f  // 1/sqrt(32)

// ---------------- scratch (device globals; no runtime alloc) ----------------
__device__ float g_qkv[(size_t)NROW * 768];       // per padded row: [q(256)|k(256)|v(256)]
__device__ float g_posqkv[WNW * 768];             // pos @ [Wq|Wk|Wv]
__device__ float g_pp[NHEAD * 81];                // posq.posk per (h,qi,ki), pre-scaled
__device__ float g_R1[(size_t)NROW * NHEAD * 9];
__device__ float g_R2[(size_t)NROW * NHEAD * 9];
__device__ float g_XX[(size_t)NROW * NHEAD * 17];
__device__ float g_ctx[(size_t)MROW * DMODEL];    // written tf32-rounded
__device__ float g_tmp[(size_t)MROW * DMODEL];
__device__ float g_res[(size_t)MROW * DMODEL];    // written tf32-rounded
__device__ float g_wT[5 * 256 * 256];             // rounded: Wq^T,Wk^T,Wv^T,Wo^T,Wout
__device__ float g_xr[(size_t)MROW * DMODEL];     // tf32-rounded copy of x

__device__ __forceinline__ float tf32r(float x) {
    uint32_t u;
    asm("cvt.rna.tf32.f32 %0, %1;" : "=r"(u) : "f"(x));
    return __uint_as_float(u);
}
__device__ __forceinline__ uint32_t smem_u32(const void* p) {
    uint32_t a;
    asm("{ .reg .u64 t; cvta.to.shared.u64 t, %1; cvt.u32.u64 %0, t; }" : "=r"(a) : "l"(p));
    return a;
}

// ---------------- K0: weights -> g_wT (tf32-rounded) ----------------
__global__ void k_wt(const float* __restrict__ Wq, const float* __restrict__ Wk,
                     const float* __restrict__ Wv, const float* __restrict__ Wo,
                     const float* __restrict__ Wout) {
    __shared__ float t[32][33];
    int z = blockIdx.z;
    int bx = blockIdx.x * 32, by = blockIdx.y * 32;
    int tid = threadIdx.x;
    int c = tid & 31, r0 = tid >> 5;
    if (z == 4) {   // plain rounded copy of Wout (already [n][k] for our use)
#pragma unroll
        for (int i = 0; i < 4; i++) {
            int r = r0 + i * 8;
            size_t idx = (size_t)(by + r) * 256 + bx + c;
            g_wT[(size_t)4 * 65536 + idx] = tf32r(Wout[idx]);
        }
        return;
    }
    const float* W = (z == 0) ? Wq : (z == 1) ? Wk : (z == 2) ? Wv : Wo;
#pragma unroll
    for (int i = 0; i < 4; i++) {
        int r = r0 + i * 8;
        t[r][c] = W[(size_t)(by + r) * 256 + bx + c];
    }
    __syncthreads();
#pragma unroll
    for (int i = 0; i < 4; i++) {
        int r = r0 + i * 8;
        g_wT[(size_t)z * 65536 + (size_t)(bx + r) * 256 + by + c] = tf32r(t[c][r]);
    }
}

// ---------------- K0b: x -> g_xr (tf32-rounded) ----------------
__global__ void k_round(const float* __restrict__ x) {
    size_t i = ((size_t)blockIdx.x * 256 + threadIdx.x) * 4;
    float4 v = *(const float4*)(x + i);
    v.x = tf32r(v.x); v.y = tf32r(v.y); v.z = tf32r(v.z); v.w = tf32r(v.w);
    *(float4*)(g_xr + i) = v;
}

// ---------------- K1: pos @ [Wq|Wk|Wv] ----------------
__global__ void k_posproj(const float* __restrict__ pos,
                          const float* __restrict__ Wq,
                          const float* __restrict__ Wk,
                          const float* __restrict__ Wv) {
    int t = blockIdx.x * blockDim.x + threadIdx.x;
    if (t >= WNW * 768) return;
    int w = t / 768, j = t % 768;
    const float* W = (j < 256) ? Wq : ((j < 512) ? Wk : Wv);
    int jj = j & 255;
    const float* p = pos + w * DMODEL;
    float acc = 0.f;
    for (int d = 0; d < DMODEL; d++) acc = fmaf(p[d], W[d * DMODEL + jj], acc);
    g_posqkv[t] = acc;
}

// ---------------- K1b: PP table ----------------
__global__ void k_pp(void) {
    int t = blockIdx.x * blockDim.x + threadIdx.x;
    if (t >= NHEAD * 81) return;
    int h = t / 81, qi = (t / 9) % 9, ki = t % 9;
    float acc = 0.f;
    const float* pq = g_posqkv + qi * 768 + h * HDIM;
    const float* pk = g_posqkv + ki * 768 + 256 + h * HDIM;
    for (int d = 0; d < HDIM; d++) acc = fmaf(pq[d], pk[d], acc);
    g_pp[t] = acc * ATT_SCALE;
}

// ---------------- tf32 mma.sync GEMM, cp.async 3-stage ----------------
// All operands pre-rounded to tf32 in GMEM. SMEM [row][16] + 2-row XOR swizzle.
// 8 warps 2(M)x4(N), each warp 64x32 via 4x4 m16n8k8 fragments.
template <int MODE>
__global__ void __launch_bounds__(256) k_tgemm(const float* __restrict__ Aglob,
                                               const float* __restrict__ addv) {
    __shared__ float As[3][2048];
    __shared__ float Bs[3][2048];
    int tid = threadIdx.x;
    int rb = blockIdx.x * 128;
    int jb = blockIdx.y * 128;

    const float* Bmat;
    int j0;
    if (MODE == 0) { Bmat = g_wT + (size_t)(blockIdx.y >> 1) * 65536; j0 = (blockIdx.y & 1) * 128; }
    else if (MODE == 1) { Bmat = g_wT + (size_t)3 * 65536; j0 = jb; }
    else { Bmat = g_wT + (size_t)4 * 65536; j0 = jb; }

    // per-thread cp.async slots: 2 for A, 2 for B
    const float* ap[2]; uint32_t azf[2];
    const float* bp[2];
    uint32_t aAddr[2], bAddr[2];
#pragma unroll
    for (int i = 0; i < 2; i++) {
        int id = tid + i * 256;
        int row = id >> 2, c4 = (id & 3) * 4;
        int soff = row * 16 + (c4 ^ (4 * ((row >> 1) & 3)));
        aAddr[i] = smem_u32(&As[0][soff]);
        bAddr[i] = smem_u32(&Bs[0][soff]);
        int gr = rb + row;
        if (MODE == 0) {
            int b = gr / PLEN;
            int r = gr - b * PLEN;
            int xr = r - PAD;
            bool av = (gr < NROW) && ((unsigned)xr < (unsigned)LSEQ);
            azf[i] = av ? 16u : 0u;
            ap[i] = Aglob + ((size_t)b * LSEQ + (size_t)((unsigned)xr < (unsigned)LSEQ ? xr : 0)) * 256 + c4;
        } else {
            azf[i] = 16u;
            ap[i] = Aglob + (size_t)gr * 256 + c4;
        }
        bp[i] = Bmat + (size_t)(j0 + row) * 256 + c4;
    }

    auto issue = [&](int chunk, int stage) {
        int kb = chunk * 16;
        uint32_t so = (uint32_t)stage * 8192;
#pragma unroll
        for (int i = 0; i < 2; i++) {
            asm volatile("cp.async.cg.shared.global [%0], [%1], 16, %2;"
                         :: "r"(aAddr[i] + so), "l"(ap[i] + kb), "r"(azf[i]) : "memory");
            asm volatile("cp.async.cg.shared.global [%0], [%1], 16;"
                         :: "r"(bAddr[i] + so), "l"(bp[i] + kb) : "memory");
        }
        asm volatile("cp.async.commit_group;" ::: "memory");
    };

    int lane = tid & 31;
    int w = tid >> 5;
    int wm = (w & 1) * 64;
    int wn = (w >> 1) * 32;
    int gid = lane >> 2;
    int tig = lane & 3;
    int swz = 4 * ((gid >> 1) & 3);

    float c[4][4][4];
#pragma unroll
    for (int mt = 0; mt < 4; mt++)
#pragma unroll
        for (int nt = 0; nt < 4; nt++)
#pragma unroll
            for (int q = 0; q < 4; q++) c[mt][nt][q] = 0.f;

    issue(0, 0);
    issue(1, 1);

#pragma unroll 1
    for (int kc = 0; kc < 16; kc++) {
        if (kc == 15) { asm volatile("cp.async.wait_group 0;" ::: "memory"); }
        else          { asm volatile("cp.async.wait_group 1;" ::: "memory"); }
        __syncthreads();
        if (kc + 2 < 16) issue(kc + 2, (kc + 2) % 3);
        int buf = kc % 3;
#pragma unroll
        for (int kh = 0; kh < 2; kh++) {
            int k0 = kh * 8;
            int ka = (k0 + tig) ^ swz;
            int kb2 = ka ^ 4;
            uint32_t af[4][4], bf[4][2];
#pragma unroll
            for (int mt = 0; mt < 4; mt++) {
                int mbase = (wm + mt * 16 + gid) * 16;
                af[mt][0] = __float_as_uint(As[buf][mbase + ka]);
                af[mt][1] = __float_as_uint(As[buf][mbase + 128 + ka]);
                af[mt][2] = __float_as_uint(As[buf][mbase + kb2]);
                af[mt][3] = __float_as_uint(As[buf][mbase + 128 + kb2]);
            }
#pragma unroll
            for (int nt = 0; nt < 4; nt++) {
                int nbase = (wn + nt * 8 + gid) * 16;
                bf[nt][0] = __float_as_uint(Bs[buf][nbase + ka]);
                bf[nt][1] = __float_as_uint(Bs[buf][nbase + kb2]);
            }
#pragma unroll
            for (int mt = 0; mt < 4; mt++)
#pragma unroll
                for (int nt = 0; nt < 4; nt++) {
                    asm volatile(
                        "mma.sync.aligned.m16n8k8.row.col.f32.tf32.tf32.f32 "
                        "{%0,%1,%2,%3}, {%4,%5,%6,%7}, {%8,%9}, {%0,%1,%2,%3};"
                        : "+f"(c[mt][nt][0]), "+f"(c[mt][nt][1]),
                          "+f"(c[mt][nt][2]), "+f"(c[mt][nt][3])
                        : "r"(af[mt][0]), "r"(af[mt][1]), "r"(af[mt][2]), "r"(af[mt][3]),
                          "r"(bf[nt][0]), "r"(bf[nt][1]));
                }
        }
        __syncthreads();
    }

    // epilogue
#pragma unroll
    for (int mt = 0; mt < 4; mt++) {
#pragma unroll
        for (int rr = 0; rr < 2; rr++) {
            int gr = rb + wm + mt * 16 + gid + rr * 8;
            if (MODE == 0 && gr >= NROW) continue;
#pragma unroll
            for (int nt = 0; nt < 4; nt++) {
                int col = wn + nt * 8 + 2 * tig;
                float v0 = c[mt][nt][rr * 2 + 0];
                float v1 = c[mt][nt][rr * 2 + 1];
                if (MODE == 0) {
                    float2* dst = (float2*)(g_qkv + (size_t)gr * 768 + jb + col);
                    *dst = make_float2(v0, v1);
                } else if (MODE == 1) {
                    const float2 a2 = *(const float2*)(addv + (size_t)gr * 256 + jb + col);
                    float2* dst = (float2*)(g_tmp + (size_t)gr * 256 + jb + col);
                    *dst = make_float2(v0 + a2.x, v1 + a2.y);
                } else {
                    const float2 r2 = *(const float2*)(g_res + (size_t)gr * 256 + jb + col);
                    const float2 b2 = *(const float2*)(addv + jb + col);
                    float2* dst = (float2*)(g_tmp + (size_t)gr * 256 + jb + col);
                    *dst = make_float2(v0 + r2.x + b2.x, v1 + r2.y + b2.y);
                }
            }
        }
    }
}

// ---------------- K3: score tables XX / R1 / R2 ----------------
#define TROWS 32
#define HALO  48
#define HSTR  33
#define RSTR  264  // 8*33
#define TAB_SMEM ((HALO + 18) * RSTR * 4)

__global__ void __launch_bounds__(256) k_tables(void) {
    extern __shared__ float sm[];
    float* s_xk = sm;                   // [48][8][33]
    float* s_pq = sm + HALO * RSTR;     // [9][8][33]
    float* s_pk = s_pq + 9 * RSTR;      // [9][8][33]
    int b = blockIdx.y;
    int r0 = blockIdx.x * TROWS;
    int tid = threadIdx.x;

    for (int idx = tid; idx < HALO * 256; idx += 256) {
        int lr = idx >> 8, d = idx & 255;
        int gr = r0 - 8 + lr;
        float v = 0.f;
        if (gr >= 0 && gr < PLEN)
            v = g_qkv[((size_t)(b * PLEN + gr)) * 768 + 256 + d];
        s_xk[lr * RSTR + (d >> 5) * HSTR + (d & 31)] = v;
    }
    for (int idx = tid; idx < 9 * 256; idx += 256) {
        int w = idx >> 8, d = idx & 255;
        int so = (d >> 5) * HSTR + (d & 31);
        s_pq[w * RSTR + so] = g_posqkv[w * 768 + d];
        s_pk[w * RSTR + so] = g_posqkv[w * 768 + 256 + d];
    }
    __syncthreads();

    int h = tid & 7, lr = tid >> 3;
    int r = r0 + lr;
    if (r >= PLEN) return;
    size_t grow = (size_t)(b * PLEN + r);

    float xq[32], xk[32];
    const float* qrow = g_qkv + grow * 768 + h * HDIM;
#pragma unroll
    for (int i = 0; i < 32; i += 4) {
        float4 v = *(const float4*)(qrow + i);
        xq[i] = v.x; xq[i + 1] = v.y; xq[i + 2] = v.z; xq[i + 3] = v.w;
    }
    const float* myk = s_xk + (lr + 8) * RSTR + h * HSTR;
#pragma unroll
    for (int i = 0; i < 32; i++) xk[i] = myk[i];

#pragma unroll
    for (int w = 0; w < 9; w++) {
        const float* pk = s_pk + w * RSTR + h * HSTR;
        float acc = 0.f;
#pragma unroll
        for (int i = 0; i < 32; i++) acc = fmaf(xq[i], pk[i], acc);
        g_R1[(grow * 8 + h) * 9 + w] = acc * ATT_SCALE;
    }
#pragma unroll
    for (int w = 0; w < 9; w++) {
        const float* pq = s_pq + w * RSTR + h * HSTR;
        float acc = 0.f;
#pragma unroll
        for (int i = 0; i < 32; i++) acc = fmaf(pq[i], xk[i], acc);
        g_R2[(grow * 8 + h) * 9 + w] = acc * ATT_SCALE;
    }
#pragma unroll
    for (int dd = 0; dd < 17; dd++) {
        int rr = r + dd - 8;
        float acc = 0.f;
        if (rr >= 0 && rr < PLEN) {
            const float* kk = s_xk + (lr + dd) * RSTR + h * HSTR;
#pragma unroll
            for (int i = 0; i < 32; i++) acc = fmaf(xq[i], kk[i], acc);
        }
        g_XX[(grow * 8 + h) * 17 + dd] = acc * ATT_SCALE;
    }
}

// ---------------- K5: softmax weights + ctx ----------------
#define WPB 16
#define ATT_SMEM ((WPB * 648 + WPB * 72 + 9 * 256 + 648) * 4)

__global__ void __launch_bounds__(256) k_attn(void) {
    extern __shared__ float sm[];
    float* s_p  = sm;                       // [WPB][8][9][9]
    float* s_w  = sm + WPB * 648;           // [WPB][8][9]
    float* s_pv = s_w + WPB * 72;           // [9][256]
    float* s_pp = s_pv + 9 * 256;           // [648]
    int tid = threadIdx.x;
    int wbase = blockIdx.x * WPB;
    int b = wbase / LSEQ;
    int n0 = wbase - b * LSEQ;

    for (int i = tid; i < 9 * 256; i += 256)
        s_pv[i] = g_posqkv[(i >> 8) * 768 + 512 + (i & 255)];
    for (int i = tid; i < 648; i += 256) s_pp[i] = g_pp[i];
    __syncthreads();

    for (int t = tid; t < WPB * 72; t += 256) {
        int wi = t / 72;
        int rem = t - wi * 72;
        int h = rem / 9, qi = rem - h * 9;
        int n = n0 + wi;
        size_t rq = (size_t)(b * PLEN + n + qi);
        const float* xx = g_XX + (rq * 8 + h) * 17 + (8 - qi);
        const float* r1 = g_R1 + (rq * 8 + h) * 9;
        float s[9], m = -1e30f;
#pragma unroll
        for (int ki = 0; ki < 9; ki++) {
            size_t rk = (size_t)(b * PLEN + n + ki);
            float v = xx[ki] + r1[ki] + g_R2[(rk * 8 + h) * 9 + qi]
                    + s_pp[h * 81 + qi * 9 + ki];
            s[ki] = v; m = fmaxf(m, v);
        }
        float sum = 0.f;
#pragma unroll
        for (int ki = 0; ki < 9; ki++) { s[ki] = __expf(s[ki] - m); sum += s[ki]; }
        float inv = 1.f / sum;
#pragma unroll
        for (int ki = 0; ki < 9; ki++)
            s_p[wi * 648 + h * 81 + qi * 9 + ki] = s[ki] * inv;
    }
    __syncthreads();

    for (int t = tid; t < WPB * 72; t += 256) {
        int wi = t / 72;
        int rem = t - wi * 72;
        int h = rem / 9, ki = rem - h * 9;
        float acc = 0.f;
#pragma unroll
        for (int qi = 0; qi < 9; qi++) acc += s_p[wi * 648 + h * 81 + qi * 9 + ki];
        s_w[wi * 72 + h * 9 + ki] = acc;
    }
    __syncthreads();

    int j = tid;
    int h = j >> 5;
    for (int wi = 0; wi < WPB; wi++) {
        int n = n0 + wi;
        float acc = 0.f;
#pragma unroll
        for (int k = 0; k < 9; k++) {
            float v = g_qkv[((size_t)(b * PLEN + n + k)) * 768 + 512 + j]
                    + s_pv[k * 256 + j];
            acc = fmaf(s_w[wi * 72 + h * 9 + k], v, acc);
        }
        g_ctx[((size_t)(b * LSEQ) + n) * 256 + j] = tf32r(acc);
    }
}

// ---------------- LayerNorm (warp per row), optional relu ----------------
__global__ void __launch_bounds__(256) k_ln(const float* __restrict__ gamma,
                                            const float* __restrict__ beta,
                                            float* __restrict__ outPtr,
                                            int mode) {
    int row = blockIdx.x * 8 + (threadIdx.x >> 5);
    int lane = threadIdx.x & 31;
    const float* p = g_tmp + (size_t)row * 256;
    float v[8], s = 0.f, s2 = 0.f;
#pragma unroll
    for (int i = 0; i < 8; i++) {
        v[i] = p[lane + i * 32];
        s += v[i]; s2 = fmaf(v[i], v[i], s2);
    }
#pragma unroll
    for (int o = 16; o; o >>= 1) {
        s  += __shfl_xor_sync(0xffffffffu, s, o);
        s2 += __shfl_xor_sync(0xffffffffu, s2, o);
    }
    float m = s * (1.f / 256.f);
    float var = s2 * (1.f / 256.f) - m * m;
    float inv = rsqrtf(var + 1e-5f);
    float* dst = mode ? outPtr : g_res;
#pragma unroll
    for (int i = 0; i < 8; i++) {
        int j = lane + i * 32;
        float o = (v[i] - m) * inv * gamma[j] + beta[j];
        if (mode) o = fmaxf(o, 0.f);
        else o = tf32r(o);          // g_res feeds the next tf32 GEMM
        dst[(size_t)row * 256 + j] = o;
    }
}

// ---------------- launch ----------------
extern "C" void kernel_launch(void* const* d_in, const int* in_sizes, int n_in,
                              void* d_out, int out_size) {
    const float* x    = (const float*)d_in[0];
    const float* Wq   = (const float*)d_in[1];
    const float* Wk   = (const float*)d_in[2];
    const float* Wv   = (const float*)d_in[3];
    const float* Wo   = (const float*)d_in[4];
    const float* pos  = (const float*)d_in[5];
    const float* Wout = (const float*)d_in[6];
    const float* bout = (const float*)d_in[7];
    const float* g1   = (const float*)d_in[8];
    const float* b1   = (const float*)d_in[9];
    const float* g2   = (const float*)d_in[10];
    const float* b2   = (const float*)d_in[11];
    float* out = (float*)d_out;

    cudaFuncSetAttribute(k_tables, cudaFuncAttributeMaxDynamicSharedMemorySize, TAB_SMEM);
    cudaFuncSetAttribute(k_attn,   cudaFuncAttributeMaxDynamicSharedMemorySize, ATT_SMEM);

    k_wt<<<dim3(8, 8, 5), 256>>>(Wq, Wk, Wv, Wo, Wout);
    k_round<<<8192, 256>>>(x);
    k_posproj<<<27, 256>>>(pos, Wq, Wk, Wv);
    k_pp<<<3, 256>>>();

    // qkv projection (tensor cores, cp.async pipeline)
    // use g_xr (rounded x) as A
    {
        float* dummy;
        cudaGetSymbolAddress((void**)&dummy, g_xr);
        k_tgemm<0><<<dim3(257, 6), 256>>>(dummy, nullptr);
    }

    // score tables
    k_tables<<<dim3(257, NB), 256, TAB_SMEM>>>();

    // attention -> ctx (rounded)
    k_attn<<<(NB * LSEQ) / WPB, 256, ATT_SMEM>>>();

    // y = x + ctx @ Wo -> g_tmp ; LN1 -> g_res (rounded)
    {
        float* actx;
        cudaGetSymbolAddress((void**)&actx, g_ctx);
        k_tgemm<1><<<dim3(256, 2), 256>>>(actx, x);
    }
    k_ln<<<4096, 256>>>(g1, b1, nullptr, 0);

    // z = g_res @ Wout^T + bout + g_res -> g_tmp ; LN2 + relu -> out
    {
        float* ares;
        cudaGetSymbolAddress((void**)&ares, g_res);
        k_tgemm<2><<<dim3(256, 2), 256>>>(ares, bout);
    }
    k_ln<<<4096, 256>>>(g2, b2, out, 1);
}